// round 2
// baseline (speedup 1.0000x reference)
#include <cuda_runtime.h>
#include <math.h>

#define D 128
#define MAXN 50000
#define MAXETOT 1700000

// ---------------- static device scratch (alloc-free) ----------------
__device__ float g_h  [MAXN * D];   // layer input (after relu), layers 2..3
__device__ float g_hw [MAXN * D];   // h @ W
__device__ float g_out[MAXN * D];   // aggregated output of current layer
__device__ float g_esrc[MAXN];
__device__ float g_edst[MAXN];
__device__ float g_m   [MAXN];      // segment max
__device__ float g_den [MAXN];      // segment sum
__device__ float g_p   [MAXETOT];   // per-edge logit, then p=exp(logit-m)

// ---------------- helpers ----------------
__device__ __forceinline__ void atomicMaxF(float* addr, float value) {
    if (value >= 0.0f)
        atomicMax((int*)addr, __float_as_int(value));
    else
        atomicMin((unsigned int*)addr, __float_as_uint(value));
}

// ---------------- SGEMM: g_hw[M,128] = A[M,128] @ W[128,128] ----------------
// A == nullptr means "read from g_h". BM=64, BN=128, BK=16, 256 threads.
__global__ void __launch_bounds__(256) gemm_kernel(const float* __restrict__ A_in,
                                                   const float* __restrict__ W, int M) {
    const float* A = A_in ? A_in : g_h;
    __shared__ float As[16][64];
    __shared__ float Bs[16][128];
    const int tid  = threadIdx.x;
    const int row0 = blockIdx.x * 64;
    const int tx   = tid & 31;   // col group (4 cols)
    const int ty   = tid >> 5;   // row group (8 rows)

    float acc[8][4];
#pragma unroll
    for (int i = 0; i < 8; i++)
#pragma unroll
        for (int j = 0; j < 4; j++) acc[i][j] = 0.0f;

    for (int k0 = 0; k0 < D; k0 += 16) {
        // load A tile (64 rows x 16 k), float4 per thread
        {
            int lin = tid * 4;
            int r   = lin >> 4;       // 0..63
            int kk  = lin & 15;       // 0,4,8,12
            int gr  = row0 + r;
            float4 av = (gr < M) ? *(const float4*)(A + (size_t)gr * D + k0 + kk)
                                 : make_float4(0.f, 0.f, 0.f, 0.f);
            As[kk + 0][r] = av.x;
            As[kk + 1][r] = av.y;
            As[kk + 2][r] = av.z;
            As[kk + 3][r] = av.w;
        }
        // load W tile (16 k x 128 cols), two float4 per thread
#pragma unroll
        for (int i = 0; i < 2; i++) {
            int s  = tid + i * 256;   // float4 slot over 512
            int bk = s >> 5;          // 0..15
            int j4 = (s & 31) * 4;
            *(float4*)&Bs[bk][j4] = *(const float4*)(W + (size_t)(k0 + bk) * D + j4);
        }
        __syncthreads();

#pragma unroll
        for (int kk = 0; kk < 16; kk++) {
            float a[8];
            float4 b4 = *(const float4*)&Bs[kk][tx * 4];
#pragma unroll
            for (int i = 0; i < 8; i++) a[i] = As[kk][ty * 8 + i];
#pragma unroll
            for (int i = 0; i < 8; i++) {
                acc[i][0] = fmaf(a[i], b4.x, acc[i][0]);
                acc[i][1] = fmaf(a[i], b4.y, acc[i][1]);
                acc[i][2] = fmaf(a[i], b4.z, acc[i][2]);
                acc[i][3] = fmaf(a[i], b4.w, acc[i][3]);
            }
        }
        __syncthreads();
    }
#pragma unroll
    for (int i = 0; i < 8; i++) {
        int gr = row0 + ty * 8 + i;
        if (gr < M)
            *(float4*)(g_hw + (size_t)gr * D + tx * 4) =
                make_float4(acc[i][0], acc[i][1], acc[i][2], acc[i][3]);
    }
}

// ---------------- per-node logits: e_src = hw.a_src, e_dst = hw.a_dst ----------------
__global__ void node_logits_kernel(const float* __restrict__ asrc,
                                   const float* __restrict__ adst, int n) {
    int gwarp = (blockIdx.x * blockDim.x + threadIdx.x) >> 5;
    int lane  = threadIdx.x & 31;
    if (gwarp >= n) return;
    const float* row = g_hw + (size_t)gwarp * D;
    float s1 = 0.f, s2 = 0.f;
#pragma unroll
    for (int c = 0; c < 4; c++) {
        float h = row[lane + 32 * c];
        s1 = fmaf(h, asrc[lane + 32 * c], s1);
        s2 = fmaf(h, adst[lane + 32 * c], s2);
    }
#pragma unroll
    for (int off = 16; off > 0; off >>= 1) {
        s1 += __shfl_down_sync(0xffffffffu, s1, off);
        s2 += __shfl_down_sync(0xffffffffu, s2, off);
    }
    if (lane == 0) { g_esrc[gwarp] = s1; g_edst[gwarp] = s2; }
}

// ---------------- per-layer init: m=-inf, den=0, out=0 ----------------
__global__ void init_kernel(int n) {
    int i = blockIdx.x * blockDim.x + threadIdx.x;
    if (i < n) { g_m[i] = -INFINITY; g_den[i] = 0.0f; }
    if (i < n * D) g_out[i] = 0.0f;
}

// ---------------- pass A: logit + segment max ----------------
__global__ void edge_logit_max_kernel(const int* __restrict__ src,
                                      const int* __restrict__ dst, int E, int n) {
    int e = blockIdx.x * blockDim.x + threadIdx.x;
    int Etot = E + n;
    if (e >= Etot) return;
    int s = (e < E) ? src[e] : (e - E);
    int d = (e < E) ? dst[e] : (e - E);
    float x = g_esrc[s] + g_edst[d];
    float lg = (x > 0.0f) ? x : 0.2f * x;
    g_p[e] = lg;
    atomicMaxF(&g_m[d], lg);
}

// ---------------- pass B: p = exp(logit - m[d]); segment sum ----------------
__global__ void edge_exp_sum_kernel(const int* __restrict__ dst, int E, int n) {
    int e = blockIdx.x * blockDim.x + threadIdx.x;
    int Etot = E + n;
    if (e >= Etot) return;
    int d = (e < E) ? dst[e] : (e - E);
    float pp = __expf(g_p[e] - g_m[d]);
    g_p[e] = pp;
    atomicAdd(&g_den[d], pp);
}

// ---------------- pass C: out[dst] += hw[src] * (p/den[dst]) ----------------
// one warp per edge, 4 floats per lane, vector reduction atomics
__global__ void __launch_bounds__(256) edge_aggregate_kernel(const int* __restrict__ src,
                                                             const int* __restrict__ dst,
                                                             int E, int n) {
    int gw   = (blockIdx.x * blockDim.x + threadIdx.x) >> 5;
    int lane = threadIdx.x & 31;
    int Etot = E + n;
    if (gw >= Etot) return;
    int s = (gw < E) ? src[gw] : (gw - E);
    int d = (gw < E) ? dst[gw] : (gw - E);
    float coef = g_p[gw] / g_den[d];  // uniform across warp (same gw)
    float4 v = *(const float4*)(g_hw + (size_t)s * D + lane * 4);
    v.x *= coef; v.y *= coef; v.z *= coef; v.w *= coef;
    float* p = g_out + (size_t)d * D + lane * 4;
    asm volatile("red.global.add.v4.f32 [%0], {%1, %2, %3, %4};"
                 :: "l"(p), "f"(v.x), "f"(v.y), "f"(v.z), "f"(v.w) : "memory");
}

// ---------------- bias + relu -> g_h ----------------
__global__ void bias_relu_kernel(const float* __restrict__ b, int n) {
    int i = blockIdx.x * blockDim.x + threadIdx.x;
    if (i >= n * D) return;
    float v = g_out[i] + b[i & (D - 1)];
    g_h[i] = fmaxf(v, 0.0f);
}

// ---------------- mean over nodes -> d_out[128] ----------------
__global__ void zero_out_kernel(float* out) {
    if (threadIdx.x < D) out[threadIdx.x] = 0.0f;
}

__global__ void mean_kernel(float* __restrict__ out, int n) {
    int j  = threadIdx.x;          // 128 threads = one column each
    int r0 = blockIdx.x * 128;
    int r1 = min(r0 + 128, n);
    float s = 0.0f;
    for (int r = r0; r < r1; r++) s += g_h[(size_t)r * D + j];
    atomicAdd(&out[j], s * (1.0f / n));
}

// ---------------- launch (kernel launches ONLY; graph-capture safe) ----------------
extern "C" void kernel_launch(void* const* d_in, const int* in_sizes, int n_in,
                              void* d_out, int out_size) {
    const float* x  = (const float*)d_in[0];
    const int*   ei = (const int*)d_in[1];
    const int n = in_sizes[0] / D;
    const int E = in_sizes[1] / 2;
    const int Etot = E + n;
    const int* src = ei;
    const int* dst = ei + E;

    for (int l = 0; l < 3; l++) {
        const float* w    = (const float*)d_in[2 + l * 4 + 0];
        const float* asrc = (const float*)d_in[2 + l * 4 + 1];
        const float* adst = (const float*)d_in[2 + l * 4 + 2];
        const float* b    = (const float*)d_in[2 + l * 4 + 3];

        // layer 0 reads external x; later layers read g_h (A == nullptr)
        gemm_kernel<<<(n + 63) / 64, 256>>>(l == 0 ? x : nullptr, w, n);
        node_logits_kernel<<<(n * 32 + 255) / 256, 256>>>(asrc, adst, n);
        init_kernel<<<(n * D + 255) / 256, 256>>>(n);
        edge_logit_max_kernel<<<(Etot + 255) / 256, 256>>>(src, dst, E, n);
        edge_exp_sum_kernel<<<(Etot + 255) / 256, 256>>>(dst, E, n);
        edge_aggregate_kernel<<<(Etot + 7) / 8, 256>>>(src, dst, E, n);
        bias_relu_kernel<<<(n * D + 255) / 256, 256>>>(b, n);
    }

    zero_out_kernel<<<1, 128>>>((float*)d_out);
    mean_kernel<<<(n + 127) / 128, 128>>>((float*)d_out, n);
}

// round 4
// speedup vs baseline: 1.9932x; 1.9932x over previous
#include <cuda_runtime.h>
#include <math.h>

#define D 128
#define MAXN 50000
#define MAXE 1700000

// ---------------- static device scratch (alloc-free) ----------------
__device__ float g_h   [MAXN * D];   // layer input (after relu)
__device__ float g_hw  [MAXN * D];   // h @ W
__device__ float g_esrc[MAXN];
__device__ float g_edst[MAXN];
__device__ int   g_cnt [MAXN];       // per-dst real-edge count
__device__ int   g_off [MAXN];       // CSR offsets (exclusive prefix of cnt)
__device__ int   g_cur [MAXN];       // scatter cursors
__device__ int   g_ssrc[MAXE];       // src ids sorted by dst

// ================= CSR build (once per launch) =================
__global__ void zero_cnt_kernel(int n) {
    int i = blockIdx.x * blockDim.x + threadIdx.x;
    if (i < n) g_cnt[i] = 0;
}

__global__ void hist_kernel(const int* __restrict__ dst, int E) {
    int e = blockIdx.x * blockDim.x + threadIdx.x;
    if (e < E) atomicAdd(&g_cnt[dst[e]], 1);
}

// single block, 1024 threads: exclusive scan of g_cnt -> g_off, g_cur
__global__ void __launch_bounds__(1024) scan_kernel(int n) {
    __shared__ int sums[1024];
    int t = threadIdx.x;
    int chunk = (n + 1023) >> 10;
    int b0 = t * chunk, b1 = min(b0 + chunk, n);
    int s = 0;
    for (int i = b0; i < b1; i++) s += g_cnt[i];
    sums[t] = s;
    __syncthreads();
    for (int off = 1; off < 1024; off <<= 1) {
        int v = (t >= off) ? sums[t - off] : 0;
        __syncthreads();
        sums[t] += v;
        __syncthreads();
    }
    int prefix = (t == 0) ? 0 : sums[t - 1];
    for (int i = b0; i < b1; i++) {
        g_off[i] = prefix;
        g_cur[i] = prefix;
        prefix += g_cnt[i];
    }
}

__global__ void scatter_kernel(const int* __restrict__ src,
                               const int* __restrict__ dst, int E) {
    int e = blockIdx.x * blockDim.x + threadIdx.x;
    if (e >= E) return;
    int p = atomicAdd(&g_cur[dst[e]], 1);
    g_ssrc[p] = src[e];
}

// ================= SGEMM: g_hw = A @ W  (A==nullptr -> g_h) =================
__global__ void __launch_bounds__(256) gemm_kernel(const float* __restrict__ A_in,
                                                   const float* __restrict__ W, int M) {
    const float* A = A_in ? A_in : g_h;
    __shared__ float As[16][64];
    __shared__ float Bs[16][128];
    const int tid  = threadIdx.x;
    const int row0 = blockIdx.x * 64;
    const int tx   = tid & 31;
    const int ty   = tid >> 5;

    float acc[8][4];
#pragma unroll
    for (int i = 0; i < 8; i++)
#pragma unroll
        for (int j = 0; j < 4; j++) acc[i][j] = 0.0f;

    for (int k0 = 0; k0 < D; k0 += 16) {
        {
            int lin = tid * 4;
            int r   = lin >> 4;
            int kk  = lin & 15;
            int gr  = row0 + r;
            float4 av = (gr < M) ? *(const float4*)(A + (size_t)gr * D + k0 + kk)
                                 : make_float4(0.f, 0.f, 0.f, 0.f);
            As[kk + 0][r] = av.x;
            As[kk + 1][r] = av.y;
            As[kk + 2][r] = av.z;
            As[kk + 3][r] = av.w;
        }
#pragma unroll
        for (int i = 0; i < 2; i++) {
            int s  = tid + i * 256;
            int bk = s >> 5;
            int j4 = (s & 31) * 4;
            *(float4*)&Bs[bk][j4] = *(const float4*)(W + (size_t)(k0 + bk) * D + j4);
        }
        __syncthreads();

#pragma unroll
        for (int kk = 0; kk < 16; kk++) {
            float a[8];
            float4 b4 = *(const float4*)&Bs[kk][tx * 4];
#pragma unroll
            for (int i = 0; i < 8; i++) a[i] = As[kk][ty * 8 + i];
#pragma unroll
            for (int i = 0; i < 8; i++) {
                acc[i][0] = fmaf(a[i], b4.x, acc[i][0]);
                acc[i][1] = fmaf(a[i], b4.y, acc[i][1]);
                acc[i][2] = fmaf(a[i], b4.z, acc[i][2]);
                acc[i][3] = fmaf(a[i], b4.w, acc[i][3]);
            }
        }
        __syncthreads();
    }
#pragma unroll
    for (int i = 0; i < 8; i++) {
        int gr = row0 + ty * 8 + i;
        if (gr < M)
            *(float4*)(g_hw + (size_t)gr * D + tx * 4) =
                make_float4(acc[i][0], acc[i][1], acc[i][2], acc[i][3]);
    }
}

// ================= per-node logits =================
__global__ void node_logits_kernel(const float* __restrict__ asrc,
                                   const float* __restrict__ adst, int n) {
    int gwarp = (blockIdx.x * blockDim.x + threadIdx.x) >> 5;
    int lane  = threadIdx.x & 31;
    if (gwarp >= n) return;
    const float* row = g_hw + (size_t)gwarp * D;
    float s1 = 0.f, s2 = 0.f;
#pragma unroll
    for (int c = 0; c < 4; c++) {
        float h = row[lane + 32 * c];
        s1 = fmaf(h, asrc[lane + 32 * c], s1);
        s2 = fmaf(h, adst[lane + 32 * c], s2);
    }
#pragma unroll
    for (int off = 16; off > 0; off >>= 1) {
        s1 += __shfl_down_sync(0xffffffffu, s1, off);
        s2 += __shfl_down_sync(0xffffffffu, s2, off);
    }
    if (lane == 0) { g_esrc[gwarp] = s1; g_edst[gwarp] = s2; }
}

// ================= fused GAT: softmax + aggregate + bias + relu =================
// one warp per dst node; atomic-free; writes g_h
__global__ void __launch_bounds__(256) gat_aggregate_kernel(const float* __restrict__ b, int n) {
    int d    = (blockIdx.x * blockDim.x + threadIdx.x) >> 5;
    int lane = threadIdx.x & 31;
    if (d >= n) return;

    const int start = g_off[d];
    const int end   = start + g_cnt[d];
    const float edst_d = g_edst[d];

    float lg_self;
    {
        float x = g_esrc[d] + edst_d;
        lg_self = (x > 0.f) ? x : 0.2f * x;
    }

    // ---- online segment softmax over real edges (per-lane, then warp combine)
    float m_l = -1e30f, s_l = 0.f;
    for (int e = start + lane; e < end; e += 32) {
        int s = g_ssrc[e];
        float x = g_esrc[s] + edst_d;
        float lg = (x > 0.f) ? x : 0.2f * x;
        if (lg > m_l) {
            s_l = fmaf(s_l, __expf(m_l - lg), 1.f);
            m_l = lg;
        } else {
            s_l += __expf(lg - m_l);
        }
    }
#pragma unroll
    for (int o = 16; o > 0; o >>= 1) {
        float m2 = __shfl_xor_sync(0xffffffffu, m_l, o);
        float s2 = __shfl_xor_sync(0xffffffffu, s_l, o);
        float M2 = fmaxf(m_l, m2);
        s_l = s_l * __expf(m_l - M2) + s2 * __expf(m2 - M2);
        m_l = M2;
    }
    const float M   = fmaxf(m_l, lg_self);
    const float den = s_l * __expf(m_l - M) + __expf(lg_self - M);
    const float inv_den = 1.0f / den;

    // ---- aggregate: self-loop contribution first
    float4 acc;
    {
        float a_self = __expf(lg_self - M) * inv_den;
        float4 v = *(const float4*)(g_hw + (size_t)d * D + lane * 4);
        acc.x = v.x * a_self; acc.y = v.y * a_self;
        acc.z = v.z * a_self; acc.w = v.w * a_self;
    }

    // ---- real edges: 32-edge chunks; lane computes alpha for "its" edge,
    //      then all lanes gather features of each edge via shuffle broadcast
    for (int base = start; base < end; base += 32) {
        int e = base + lane;
        int s = 0;
        float alpha = 0.f;
        if (e < end) {
            s = g_ssrc[e];
            float x = g_esrc[s] + edst_d;
            float lg = (x > 0.f) ? x : 0.2f * x;
            alpha = __expf(lg - M) * inv_den;
        }
        int c = min(32, end - base);
        for (int j = 0; j < c; j++) {
            float a  = __shfl_sync(0xffffffffu, alpha, j);
            int   sj = __shfl_sync(0xffffffffu, s, j);
            float4 v = *(const float4*)(g_hw + (size_t)sj * D + lane * 4);
            acc.x = fmaf(v.x, a, acc.x);
            acc.y = fmaf(v.y, a, acc.y);
            acc.z = fmaf(v.z, a, acc.z);
            acc.w = fmaf(v.w, a, acc.w);
        }
    }

    // ---- bias + relu, store for next layer
    float4 bb = *(const float4*)(b + lane * 4);
    float4 o;
    o.x = fmaxf(acc.x + bb.x, 0.f);
    o.y = fmaxf(acc.y + bb.y, 0.f);
    o.z = fmaxf(acc.z + bb.z, 0.f);
    o.w = fmaxf(acc.w + bb.w, 0.f);
    *(float4*)(g_h + (size_t)d * D + lane * 4) = o;
}

// ================= mean over nodes -> d_out[128] =================
__global__ void zero_out_kernel(float* out) {
    if (threadIdx.x < D) out[threadIdx.x] = 0.0f;
}

__global__ void mean_kernel(float* __restrict__ out, int n) {
    int j  = threadIdx.x;
    int r0 = blockIdx.x * 128;
    int r1 = min(r0 + 128, n);
    float s = 0.0f;
    for (int r = r0; r < r1; r++) s += g_h[(size_t)r * D + j];
    atomicAdd(&out[j], s * (1.0f / n));
}

// ================= launch (kernel launches only) =================
extern "C" void kernel_launch(void* const* d_in, const int* in_sizes, int n_in,
                              void* d_out, int out_size) {
    const float* x  = (const float*)d_in[0];
    const int*   ei = (const int*)d_in[1];
    const int n = in_sizes[0] / D;
    const int E = in_sizes[1] / 2;
    const int* src = ei;
    const int* dst = ei + E;

    // CSR by dst (graph identical across layers)
    zero_cnt_kernel<<<(n + 255) / 256, 256>>>(n);
    hist_kernel<<<(E + 255) / 256, 256>>>(dst, E);
    scan_kernel<<<1, 1024>>>(n);
    scatter_kernel<<<(E + 255) / 256, 256>>>(src, dst, E);

    for (int l = 0; l < 3; l++) {
        const float* w    = (const float*)d_in[2 + l * 4 + 0];
        const float* asrc = (const float*)d_in[2 + l * 4 + 1];
        const float* adst = (const float*)d_in[2 + l * 4 + 2];
        const float* b    = (const float*)d_in[2 + l * 4 + 3];

        gemm_kernel<<<(n + 63) / 64, 256>>>(l == 0 ? x : nullptr, w, n);
        node_logits_kernel<<<(n * 32 + 255) / 256, 256>>>(asrc, adst, n);
        gat_aggregate_kernel<<<(n * 32 + 255) / 256, 256>>>(b, n);
    }

    zero_out_kernel<<<1, 128>>>((float*)d_out);
    mean_kernel<<<(n + 127) / 128, 128>>>((float*)d_out, n);
}

// round 5
// speedup vs baseline: 2.0532x; 1.0301x over previous
#include <cuda_runtime.h>
#include <cuda_fp16.h>
#include <math.h>

#define D 128
#define MAXN 50000
#define MAXE 1700000

// ---------------- static device scratch (alloc-free) ----------------
__device__ float   g_h   [MAXN * D];    // layer input (after relu), fp32
__device__ __half2 g_hwh [MAXN * 64];   // h @ W in fp16 (64 half2 per row)
__device__ float   g_esrc[MAXN];
__device__ float   g_edst[MAXN];
__device__ int     g_cnt [MAXN];        // per-dst real-edge count
__device__ int     g_off [MAXN];        // CSR offsets
__device__ int     g_cur [MAXN];        // scatter cursors
__device__ int     g_ssrc[MAXE];        // src ids sorted by dst

// ================= CSR build (once per launch) =================
__global__ void zero_cnt_kernel(int n) {
    int i = blockIdx.x * blockDim.x + threadIdx.x;
    if (i < n) g_cnt[i] = 0;
}

__global__ void hist_kernel(const int* __restrict__ dst, int E) {
    int e = blockIdx.x * blockDim.x + threadIdx.x;
    if (e < E) atomicAdd(&g_cnt[dst[e]], 1);
}

__global__ void __launch_bounds__(1024) scan_kernel(int n) {
    __shared__ int sums[1024];
    int t = threadIdx.x;
    int chunk = (n + 1023) >> 10;
    int b0 = t * chunk, b1 = min(b0 + chunk, n);
    int s = 0;
    for (int i = b0; i < b1; i++) s += g_cnt[i];
    sums[t] = s;
    __syncthreads();
    for (int off = 1; off < 1024; off <<= 1) {
        int v = (t >= off) ? sums[t - off] : 0;
        __syncthreads();
        sums[t] += v;
        __syncthreads();
    }
    int prefix = (t == 0) ? 0 : sums[t - 1];
    for (int i = b0; i < b1; i++) {
        g_off[i] = prefix;
        g_cur[i] = prefix;
        prefix += g_cnt[i];
    }
}

__global__ void scatter_kernel(const int* __restrict__ src,
                               const int* __restrict__ dst, int E) {
    int e = blockIdx.x * blockDim.x + threadIdx.x;
    if (e >= E) return;
    int p = atomicAdd(&g_cur[dst[e]], 1);
    g_ssrc[p] = src[e];
}

// ================= SGEMM + fused logits =================
// g_hwh = half(A @ W); g_esrc/g_edst = (A@W).asrc/adst in fp32.
// A == nullptr -> read g_h. BM=64, BN=128(full), BK=16, 256 threads.
__global__ void __launch_bounds__(256) gemm_kernel(const float* __restrict__ A_in,
                                                   const float* __restrict__ W,
                                                   const float* __restrict__ asrc,
                                                   const float* __restrict__ adst,
                                                   int M) {
    const float* A = A_in ? A_in : g_h;
    __shared__ float As[16][64];
    __shared__ float Bs[16][128];
    const int tid  = threadIdx.x;
    const int row0 = blockIdx.x * 64;
    const int tx   = tid & 31;   // col group (4 cols)
    const int ty   = tid >> 5;   // row group (8 rows)

    float acc[8][4];
#pragma unroll
    for (int i = 0; i < 8; i++)
#pragma unroll
        for (int j = 0; j < 4; j++) acc[i][j] = 0.0f;

    for (int k0 = 0; k0 < D; k0 += 16) {
        {
            int lin = tid * 4;
            int r   = lin >> 4;
            int kk  = lin & 15;
            int gr  = row0 + r;
            float4 av = (gr < M) ? *(const float4*)(A + (size_t)gr * D + k0 + kk)
                                 : make_float4(0.f, 0.f, 0.f, 0.f);
            As[kk + 0][r] = av.x;
            As[kk + 1][r] = av.y;
            As[kk + 2][r] = av.z;
            As[kk + 3][r] = av.w;
        }
#pragma unroll
        for (int i = 0; i < 2; i++) {
            int s  = tid + i * 256;
            int bk = s >> 5;
            int j4 = (s & 31) * 4;
            *(float4*)&Bs[bk][j4] = *(const float4*)(W + (size_t)(k0 + bk) * D + j4);
        }
        __syncthreads();

#pragma unroll
        for (int kk = 0; kk < 16; kk++) {
            float a[8];
            float4 b4 = *(const float4*)&Bs[kk][tx * 4];
#pragma unroll
            for (int i = 0; i < 8; i++) a[i] = As[kk][ty * 8 + i];
#pragma unroll
            for (int i = 0; i < 8; i++) {
                acc[i][0] = fmaf(a[i], b4.x, acc[i][0]);
                acc[i][1] = fmaf(a[i], b4.y, acc[i][1]);
                acc[i][2] = fmaf(a[i], b4.z, acc[i][2]);
                acc[i][3] = fmaf(a[i], b4.w, acc[i][3]);
            }
        }
        __syncthreads();
    }

    // ---- store fp16 hw + fused per-row logits (warp owns full rows)
    const float4 avs = *(const float4*)(asrc + tx * 4);
    const float4 avd = *(const float4*)(adst + tx * 4);
#pragma unroll
    for (int i = 0; i < 8; i++) {
        int gr = row0 + ty * 8 + i;
        float s1 = acc[i][0] * avs.x + acc[i][1] * avs.y + acc[i][2] * avs.z + acc[i][3] * avs.w;
        float s2 = acc[i][0] * avd.x + acc[i][1] * avd.y + acc[i][2] * avd.z + acc[i][3] * avd.w;
#pragma unroll
        for (int o = 16; o > 0; o >>= 1) {
            s1 += __shfl_xor_sync(0xffffffffu, s1, o);
            s2 += __shfl_xor_sync(0xffffffffu, s2, o);
        }
        if (gr < M) {
            __half2 h0 = __floats2half2_rn(acc[i][0], acc[i][1]);
            __half2 h1 = __floats2half2_rn(acc[i][2], acc[i][3]);
            uint2 u;
            u.x = *(unsigned int*)&h0;
            u.y = *(unsigned int*)&h1;
            *(uint2*)(g_hwh + (size_t)gr * 64 + tx * 2) = u;
            if (tx == 0) { g_esrc[gr] = s1; g_edst[gr] = s2; }
        }
    }
}

// ================= fused GAT: softmax + aggregate + bias + relu =================
// one warp per dst node; atomic-free; fp16 gathers; writes g_h (fp32)
__global__ void __launch_bounds__(256) gat_aggregate_kernel(const float* __restrict__ b, int n) {
    int d    = (blockIdx.x * blockDim.x + threadIdx.x) >> 5;
    int lane = threadIdx.x & 31;
    if (d >= n) return;

    const int start = g_off[d];
    const int end   = start + g_cnt[d];
    const float edst_d = g_edst[d];

    float lg_self;
    {
        float x = g_esrc[d] + edst_d;
        lg_self = (x > 0.f) ? x : 0.2f * x;
    }

    // ---- online segment softmax over real edges
    float m_l = -1e30f, s_l = 0.f;
    for (int e = start + lane; e < end; e += 32) {
        int s = g_ssrc[e];
        float x = g_esrc[s] + edst_d;
        float lg = (x > 0.f) ? x : 0.2f * x;
        if (lg > m_l) {
            s_l = fmaf(s_l, __expf(m_l - lg), 1.f);
            m_l = lg;
        } else {
            s_l += __expf(lg - m_l);
        }
    }
#pragma unroll
    for (int o = 16; o > 0; o >>= 1) {
        float m2 = __shfl_xor_sync(0xffffffffu, m_l, o);
        float s2 = __shfl_xor_sync(0xffffffffu, s_l, o);
        float M2 = fmaxf(m_l, m2);
        s_l = s_l * __expf(m_l - M2) + s2 * __expf(m2 - M2);
        m_l = M2;
    }
    const float M   = fmaxf(m_l, lg_self);
    const float den = s_l * __expf(m_l - M) + __expf(lg_self - M);
    const float inv_den = 1.0f / den;

    // ---- self-loop contribution
    float4 acc;
    {
        float a_self = __expf(lg_self - M) * inv_den;
        uint2 u = *(const uint2*)(g_hwh + (size_t)d * 64 + lane * 2);
        float2 fa = __half22float2(*(__half2*)&u.x);
        float2 fb = __half22float2(*(__half2*)&u.y);
        acc.x = fa.x * a_self; acc.y = fa.y * a_self;
        acc.z = fb.x * a_self; acc.w = fb.y * a_self;
    }

    // ---- real edges: 32-edge chunks, shuffle-broadcast gather
    for (int base = start; base < end; base += 32) {
        int e = base + lane;
        int s = 0;
        float alpha = 0.f;
        if (e < end) {
            s = g_ssrc[e];
            float x = g_esrc[s] + edst_d;
            float lg = (x > 0.f) ? x : 0.2f * x;
            alpha = __expf(lg - M) * inv_den;
        }
        int c = min(32, end - base);
        for (int j = 0; j < c; j++) {
            float a  = __shfl_sync(0xffffffffu, alpha, j);
            int   sj = __shfl_sync(0xffffffffu, s, j);
            uint2 u = *(const uint2*)(g_hwh + (size_t)sj * 64 + lane * 2);
            float2 fa = __half22float2(*(__half2*)&u.x);
            float2 fb = __half22float2(*(__half2*)&u.y);
            acc.x = fmaf(fa.x, a, acc.x);
            acc.y = fmaf(fa.y, a, acc.y);
            acc.z = fmaf(fb.x, a, acc.z);
            acc.w = fmaf(fb.y, a, acc.w);
        }
    }

    // ---- bias + relu, store for next layer
    float4 bb = *(const float4*)(b + lane * 4);
    float4 o;
    o.x = fmaxf(acc.x + bb.x, 0.f);
    o.y = fmaxf(acc.y + bb.y, 0.f);
    o.z = fmaxf(acc.z + bb.z, 0.f);
    o.w = fmaxf(acc.w + bb.w, 0.f);
    *(float4*)(g_h + (size_t)d * D + lane * 4) = o;
}

// ================= mean over nodes -> d_out[128] =================
__global__ void zero_out_kernel(float* out) {
    if (threadIdx.x < D) out[threadIdx.x] = 0.0f;
}

__global__ void mean_kernel(float* __restrict__ out, int n) {
    int j  = threadIdx.x;
    int r0 = blockIdx.x * 128;
    int r1 = min(r0 + 128, n);
    float s = 0.0f;
    for (int r = r0; r < r1; r++) s += g_h[(size_t)r * D + j];
    atomicAdd(&out[j], s * (1.0f / n));
}

// ================= launch (kernel launches only) =================
extern "C" void kernel_launch(void* const* d_in, const int* in_sizes, int n_in,
                              void* d_out, int out_size) {
    const float* x  = (const float*)d_in[0];
    const int*   ei = (const int*)d_in[1];
    const int n = in_sizes[0] / D;
    const int E = in_sizes[1] / 2;
    const int* src = ei;
    const int* dst = ei + E;

    // CSR by dst (graph identical across layers)
    zero_cnt_kernel<<<(n + 255) / 256, 256>>>(n);
    hist_kernel<<<(E + 255) / 256, 256>>>(dst, E);
    scan_kernel<<<1, 1024>>>(n);
    scatter_kernel<<<(E + 255) / 256, 256>>>(src, dst, E);

    for (int l = 0; l < 3; l++) {
        const float* w    = (const float*)d_in[2 + l * 4 + 0];
        const float* asrc = (const float*)d_in[2 + l * 4 + 1];
        const float* adst = (const float*)d_in[2 + l * 4 + 2];
        const float* b    = (const float*)d_in[2 + l * 4 + 3];

        gemm_kernel<<<(n + 63) / 64, 256>>>(l == 0 ? x : nullptr, w, asrc, adst, n);
        gat_aggregate_kernel<<<(n * 32 + 255) / 256, 256>>>(b, n);
    }

    zero_out_kernel<<<1, 128>>>((float*)d_out);
    mean_kernel<<<(n + 127) / 128, 128>>>((float*)d_out, n);
}

// round 8
// speedup vs baseline: 2.7515x; 1.3401x over previous
#include <cuda_runtime.h>
#include <cuda_fp16.h>
#include <math.h>

#define D 128
#define MAXN 50000
#define MAXE 1700000

// ---------------- static device scratch (alloc-free) ----------------
__device__ __half2 g_h   [MAXN * 64];   // layer input (after relu), fp16, row-major 128
__device__ __half2 g_hwh [MAXN * 64];   // h @ W, fp16
__device__ float   g_esrc[MAXN];
__device__ float   g_edst[MAXN];
__device__ int     g_cnt [MAXN];
__device__ int     g_off [MAXN];
__device__ int     g_cur [MAXN];
__device__ int     g_ssrc[MAXE];

// ================= CSR build (once per launch) =================
__global__ void zero_cnt_kernel(int n) {
    int i = blockIdx.x * blockDim.x + threadIdx.x;
    if (i < n) g_cnt[i] = 0;
}

__global__ void hist_kernel(const int* __restrict__ dst, int E) {
    int e = blockIdx.x * blockDim.x + threadIdx.x;
    if (e < E) atomicAdd(&g_cnt[dst[e]], 1);
}

__global__ void __launch_bounds__(1024) scan_kernel(int n) {
    __shared__ int sums[1024];
    int t = threadIdx.x;
    int chunk = (n + 1023) >> 10;
    int b0 = t * chunk, b1 = min(b0 + chunk, n);
    int s = 0;
    for (int i = b0; i < b1; i++) s += g_cnt[i];
    sums[t] = s;
    __syncthreads();
    for (int off = 1; off < 1024; off <<= 1) {
        int v = (t >= off) ? sums[t - off] : 0;
        __syncthreads();
        sums[t] += v;
        __syncthreads();
    }
    int prefix = (t == 0) ? 0 : sums[t - 1];
    for (int i = b0; i < b1; i++) {
        g_off[i] = prefix;
        g_cur[i] = prefix;
        prefix += g_cnt[i];
    }
}

__global__ void scatter_kernel(const int* __restrict__ src,
                               const int* __restrict__ dst, int E) {
    int e = blockIdx.x * blockDim.x + threadIdx.x;
    if (e >= E) return;
    int p = atomicAdd(&g_cur[dst[e]], 1);
    g_ssrc[p] = src[e];
}

// ================= convert x (fp32) -> g_h (fp16), once =================
__global__ void conv_x_kernel(const float* __restrict__ x, int total_h2) {
    int i = blockIdx.x * blockDim.x + threadIdx.x;
    if (i >= total_h2) return;
    float2 v = ((const float2*)x)[i];
    g_h[i] = __floats2half2_rn(v.x, v.y);
}

// ================= HMMA GEMM + fused logits =================
// g_hwh = half(g_h @ W); g_esrc/g_edst from fp32 accumulators.
// block: 128 rows, 256 threads (8 warps, 16 rows/warp). W staged to smem transposed.
__global__ void __launch_bounds__(256) hgemm_kernel(const float* __restrict__ W,
                                                    const float* __restrict__ asrc,
                                                    const float* __restrict__ adst,
                                                    int M) {
    // Wt in smem: smWt[n*136 + k] = W[k][n]; stride 136 halfs = 68 words
    __shared__ __half smWt[128 * 136];
    const int tid  = threadIdx.x;
    const int wid  = tid >> 5;
    const int lane = tid & 31;
    const int g    = lane >> 2;
    const int tg   = lane & 3;

    for (int idx = tid; idx < 128 * 128; idx += 256) {
        int k = idx >> 7, nn = idx & 127;
        smWt[nn * 136 + k] = __float2half(W[idx]);
    }
    __syncthreads();

    const __half* Ah = (const __half*)g_h;
    const int r0 = blockIdx.x * 128 + wid * 16 + g;
    const int r1 = r0 + 8;
    const bool v0 = r0 < M, v1 = r1 < M;

    float acc[16][4];
#pragma unroll
    for (int nt = 0; nt < 16; nt++)
#pragma unroll
        for (int j = 0; j < 4; j++) acc[nt][j] = 0.0f;

#pragma unroll
    for (int kstep = 0; kstep < 8; kstep++) {
        const int k0 = kstep * 16 + tg * 2;
        unsigned a0 = v0 ? *(const unsigned*)(Ah + (size_t)r0 * 128 + k0)     : 0u;
        unsigned a1 = v1 ? *(const unsigned*)(Ah + (size_t)r1 * 128 + k0)     : 0u;
        unsigned a2 = v0 ? *(const unsigned*)(Ah + (size_t)r0 * 128 + k0 + 8) : 0u;
        unsigned a3 = v1 ? *(const unsigned*)(Ah + (size_t)r1 * 128 + k0 + 8) : 0u;
#pragma unroll
        for (int nt = 0; nt < 16; nt++) {
            int n = nt * 8 + g;
            unsigned b0 = *(const unsigned*)(smWt + n * 136 + k0);
            unsigned b1 = *(const unsigned*)(smWt + n * 136 + k0 + 8);
            asm volatile(
                "mma.sync.aligned.m16n8k16.row.col.f32.f16.f16.f32 "
                "{%0,%1,%2,%3}, {%4,%5,%6,%7}, {%8,%9}, {%0,%1,%2,%3};"
                : "+f"(acc[nt][0]), "+f"(acc[nt][1]), "+f"(acc[nt][2]), "+f"(acc[nt][3])
                : "r"(a0), "r"(a1), "r"(a2), "r"(a3), "r"(b0), "r"(b1));
        }
    }

    // ---- fused logits: rows r0 (c0,c1) and r1 (c2,c3); cols nt*8 + tg*2 {+1}
    float sls = 0.f, sld = 0.f, shs = 0.f, shd = 0.f;
#pragma unroll
    for (int nt = 0; nt < 16; nt++) {
        float2 avs = ((const float2*)asrc)[nt * 4 + tg];
        float2 avd = ((const float2*)adst)[nt * 4 + tg];
        sls += acc[nt][0] * avs.x + acc[nt][1] * avs.y;
        sld += acc[nt][0] * avd.x + acc[nt][1] * avd.y;
        shs += acc[nt][2] * avs.x + acc[nt][3] * avs.y;
        shd += acc[nt][2] * avd.x + acc[nt][3] * avd.y;
    }
#pragma unroll
    for (int o = 1; o <= 2; o <<= 1) {
        sls += __shfl_xor_sync(0xffffffffu, sls, o);
        sld += __shfl_xor_sync(0xffffffffu, sld, o);
        shs += __shfl_xor_sync(0xffffffffu, shs, o);
        shd += __shfl_xor_sync(0xffffffffu, shd, o);
    }

    if (v0) {
#pragma unroll
        for (int nt = 0; nt < 16; nt++)
            g_hwh[(size_t)r0 * 64 + nt * 4 + tg] = __floats2half2_rn(acc[nt][0], acc[nt][1]);
        if (tg == 0) { g_esrc[r0] = sls; g_edst[r0] = sld; }
    }
    if (v1) {
#pragma unroll
        for (int nt = 0; nt < 16; nt++)
            g_hwh[(size_t)r1 * 64 + nt * 4 + tg] = __floats2half2_rn(acc[nt][2], acc[nt][3]);
        if (tg == 0) { g_esrc[r1] = shs; g_edst[r1] = shd; }
    }
}

// ================= fused GAT: softmax + aggregate + bias + relu =================
// one warp per dst node; atomic-free; unrolled high-MLP fp16 gathers; writes g_h (fp16)
__global__ void __launch_bounds__(256) gat_aggregate_kernel(const float* __restrict__ b, int n) {
    int d    = (blockIdx.x * blockDim.x + threadIdx.x) >> 5;
    int lane = threadIdx.x & 31;
    if (d >= n) return;

    const int start = g_off[d];
    const int end   = start + g_cnt[d];
    const float edst_d = g_edst[d];

    float lg_self;
    {
        float x = g_esrc[d] + edst_d;
        lg_self = (x > 0.f) ? x : 0.2f * x;
    }

    // ---- online segment softmax over real edges
    float m_l = -1e30f, s_l = 0.f;
    for (int e = start + lane; e < end; e += 32) {
        int s = g_ssrc[e];
        float x = g_esrc[s] + edst_d;
        float lg = (x > 0.f) ? x : 0.2f * x;
        if (lg > m_l) {
            s_l = fmaf(s_l, __expf(m_l - lg), 1.f);
            m_l = lg;
        } else {
            s_l += __expf(lg - m_l);
        }
    }
#pragma unroll
    for (int o = 16; o > 0; o >>= 1) {
        float m2 = __shfl_xor_sync(0xffffffffu, m_l, o);
        float s2 = __shfl_xor_sync(0xffffffffu, s_l, o);
        float M2 = fmaxf(m_l, m2);
        s_l = s_l * __expf(m_l - M2) + s2 * __expf(m2 - M2);
        m_l = M2;
    }
    const float M   = fmaxf(m_l, lg_self);
    const float den = s_l * __expf(m_l - M) + __expf(lg_self - M);
    const float inv_den = 1.0f / den;

    // ---- self-loop contribution
    float4 acc;
    {
        float a_self = __expf(lg_self - M) * inv_den;
        uint2 u = *(const uint2*)(g_hwh + (size_t)d * 64 + lane * 2);
        float2 fa = __half22float2(*(__half2*)&u.x);
        float2 fb = __half22float2(*(__half2*)&u.y);
        acc.x = fa.x * a_self; acc.y = fa.y * a_self;
        acc.z = fb.x * a_self; acc.w = fb.y * a_self;
    }

    // ---- full 32-edge chunks: fully unrolled, 4 independent gathers per group
    int base = start;
    for (; base + 32 <= end; base += 32) {
        int s = g_ssrc[base + lane];
        float x = g_esrc[s] + edst_d;
        float lg = (x > 0.f) ? x : 0.2f * x;
        float alpha = __expf(lg - M) * inv_den;
#pragma unroll
        for (int j = 0; j < 32; j += 4) {
            float a0 = __shfl_sync(0xffffffffu, alpha, j + 0);
            float a1 = __shfl_sync(0xffffffffu, alpha, j + 1);
            float a2 = __shfl_sync(0xffffffffu, alpha, j + 2);
            float a3 = __shfl_sync(0xffffffffu, alpha, j + 3);
            int s0 = __shfl_sync(0xffffffffu, s, j + 0);
            int s1 = __shfl_sync(0xffffffffu, s, j + 1);
            int s2 = __shfl_sync(0xffffffffu, s, j + 2);
            int s3 = __shfl_sync(0xffffffffu, s, j + 3);
            uint2 u0 = *(const uint2*)(g_hwh + (size_t)s0 * 64 + lane * 2);
            uint2 u1 = *(const uint2*)(g_hwh + (size_t)s1 * 64 + lane * 2);
            uint2 u2 = *(const uint2*)(g_hwh + (size_t)s2 * 64 + lane * 2);
            uint2 u3 = *(const uint2*)(g_hwh + (size_t)s3 * 64 + lane * 2);
            float2 fa, fb;
            fa = __half22float2(*(__half2*)&u0.x); fb = __half22float2(*(__half2*)&u0.y);
            acc.x = fmaf(fa.x, a0, acc.x); acc.y = fmaf(fa.y, a0, acc.y);
            acc.z = fmaf(fb.x, a0, acc.z); acc.w = fmaf(fb.y, a0, acc.w);
            fa = __half22float2(*(__half2*)&u1.x); fb = __half22float2(*(__half2*)&u1.y);
            acc.x = fmaf(fa.x, a1, acc.x); acc.y = fmaf(fa.y, a1, acc.y);
            acc.z = fmaf(fb.x, a1, acc.z); acc.w = fmaf(fb.y, a1, acc.w);
            fa = __half22float2(*(__half2*)&u2.x); fb = __half22float2(*(__half2*)&u2.y);
            acc.x = fmaf(fa.x, a2, acc.x); acc.y = fmaf(fa.y, a2, acc.y);
            acc.z = fmaf(fb.x, a2, acc.z); acc.w = fmaf(fb.y, a2, acc.w);
            fa = __half22float2(*(__half2*)&u3.x); fb = __half22float2(*(__half2*)&u3.y);
            acc.x = fmaf(fa.x, a3, acc.x); acc.y = fmaf(fa.y, a3, acc.y);
            acc.z = fmaf(fb.x, a3, acc.z); acc.w = fmaf(fb.y, a3, acc.w);
        }
    }
    // ---- tail chunk (< 32 edges)
    if (base < end) {
        int e = base + lane;
        int s = 0;
        float alpha = 0.f;
        if (e < end) {
            s = g_ssrc[e];
            float x = g_esrc[s] + edst_d;
            float lg = (x > 0.f) ? x : 0.2f * x;
            alpha = __expf(lg - M) * inv_den;
        }
        int c = end - base;
        for (int j = 0; j < c; j++) {
            float a  = __shfl_sync(0xffffffffu, alpha, j);
            int   sj = __shfl_sync(0xffffffffu, s, j);
            uint2 u = *(const uint2*)(g_hwh + (size_t)sj * 64 + lane * 2);
            float2 fa = __half22float2(*(__half2*)&u.x);
            float2 fb = __half22float2(*(__half2*)&u.y);
            acc.x = fmaf(fa.x, a, acc.x);
            acc.y = fmaf(fa.y, a, acc.y);
            acc.z = fmaf(fb.x, a, acc.z);
            acc.w = fmaf(fb.y, a, acc.w);
        }
    }

    // ---- bias + relu, store fp16 for next layer
    float4 bb = *(const float4*)(b + lane * 4);
    uint2 o;
    __half2 o0 = __floats2half2_rn(fmaxf(acc.x + bb.x, 0.f), fmaxf(acc.y + bb.y, 0.f));
    __half2 o1 = __floats2half2_rn(fmaxf(acc.z + bb.z, 0.f), fmaxf(acc.w + bb.w, 0.f));
    o.x = *(unsigned*)&o0;
    o.y = *(unsigned*)&o1;
    *(uint2*)(g_h + (size_t)d * 64 + lane * 2) = o;
}

// ================= mean over nodes -> d_out[128] =================
__global__ void zero_out_kernel(float* out) {
    if (threadIdx.x < D) out[threadIdx.x] = 0.0f;
}

__global__ void mean_kernel(float* __restrict__ out, int n) {
    int j  = threadIdx.x;          // column 0..127
    int r0 = blockIdx.x * 128;
    int r1 = min(r0 + 128, n);
    float s = 0.0f;
    for (int r = r0; r < r1; r++) {
        __half2 v = g_h[(size_t)r * 64 + (j >> 1)];
        s += (j & 1) ? __high2float(v) : __low2float(v);
    }
    atomicAdd(&out[j], s * (1.0f / n));
}

// ================= launch (kernel launches only) =================
extern "C" void kernel_launch(void* const* d_in, const int* in_sizes, int n_in,
                              void* d_out, int out_size) {
    const float* x  = (const float*)d_in[0];
    const int*   ei = (const int*)d_in[1];
    const int n = in_sizes[0] / D;
    const int E = in_sizes[1] / 2;
    const int* src = ei;
    const int* dst = ei + E;

    // CSR by dst (graph identical across layers)
    zero_cnt_kernel<<<(n + 255) / 256, 256>>>(n);
    hist_kernel<<<(E + 255) / 256, 256>>>(dst, E);
    scan_kernel<<<1, 1024>>>(n);
    scatter_kernel<<<(E + 255) / 256, 256>>>(src, dst, E);

    // x -> fp16
    conv_x_kernel<<<(n * 64 + 255) / 256, 256>>>(x, n * 64);

    for (int l = 0; l < 3; l++) {
        const float* w    = (const float*)d_in[2 + l * 4 + 0];
        const float* asrc = (const float*)d_in[2 + l * 4 + 1];
        const float* adst = (const float*)d_in[2 + l * 4 + 2];
        const float* b    = (const float*)d_in[2 + l * 4 + 3];

        hgemm_kernel<<<(n + 127) / 128, 256>>>(w, asrc, adst, n);
        gat_aggregate_kernel<<<(n * 32 + 255) / 256, 256>>>(b, n);
    }

    zero_out_kernel<<<1, 128>>>((float*)d_out);
    mean_kernel<<<(n + 127) / 128, 128>>>((float*)d_out, n);
}